// round 1
// baseline (speedup 1.0000x reference)
#include <cuda_runtime.h>
#include <math.h>

// Problem constants
#define B_   8
#define C_   128
#define L_   2048
#define H_   4
#define D_   32
#define OC3  384    // 3*C

// Scratch (static device globals — no runtime allocation)
__device__ float g_qkv[B_ * OC3 * L_];     // [b][o][l], o in [0,384): part*128 + h*32 + d
__device__ float g_attno[B_ * C_ * L_];    // [b][h*32+d][l]  (attention output, pre-proj)

// ---------------------------------------------------------------------------
// Generic 1x1-conv GEMM: out[o][l] = sum_c W[o][c] * X[c][l] + bias[o] (+res)
// 64x64 tile per block, 256 threads, 4x4 register blocking, K-chunks of 32.
// ---------------------------------------------------------------------------
template<bool RESID>
__device__ __forceinline__ void gemm_body(
    const float* __restrict__ W, const float* __restrict__ Xb,
    const float* __restrict__ bias, const float* __restrict__ resb,
    float* __restrict__ outb)
{
    __shared__ __align__(16) float w_s[64][33];
    __shared__ __align__(16) float x_s[32][68];

    const int o0 = blockIdx.y * 64;
    const int l0 = blockIdx.x * 64;
    const int tid = threadIdx.x;
    const int ty = tid >> 4;      // 0..15 (row group)
    const int tx = tid & 15;      // 0..15 (col group)

    float acc[4][4] = {};

    for (int c0 = 0; c0 < C_; c0 += 32) {
        __syncthreads();
        #pragma unroll
        for (int i = 0; i < 8; i++) {
            int idx = i * 256 + tid;
            int r = idx >> 5, cc = idx & 31;
            w_s[r][cc] = W[(o0 + r) * C_ + c0 + cc];
        }
        #pragma unroll
        for (int i = 0; i < 8; i++) {
            int idx = i * 256 + tid;
            int r = idx >> 6, cl = idx & 63;
            x_s[r][cl] = Xb[(c0 + r) * L_ + l0 + cl];
        }
        __syncthreads();

        #pragma unroll
        for (int cc = 0; cc < 32; cc++) {
            float4 bv = *(const float4*)&x_s[cc][tx * 4];
            float a[4];
            #pragma unroll
            for (int i = 0; i < 4; i++) a[i] = w_s[ty * 4 + i][cc];
            #pragma unroll
            for (int i = 0; i < 4; i++) {
                acc[i][0] = fmaf(a[i], bv.x, acc[i][0]);
                acc[i][1] = fmaf(a[i], bv.y, acc[i][1]);
                acc[i][2] = fmaf(a[i], bv.z, acc[i][2]);
                acc[i][3] = fmaf(a[i], bv.w, acc[i][3]);
            }
        }
    }

    #pragma unroll
    for (int i = 0; i < 4; i++) {
        int o = o0 + ty * 4 + i;
        float bb = bias[o];
        float4 r4;
        r4.x = acc[i][0] + bb;
        r4.y = acc[i][1] + bb;
        r4.z = acc[i][2] + bb;
        r4.w = acc[i][3] + bb;
        if (RESID) {
            float4 rr = *(const float4*)&resb[o * L_ + l0 + tx * 4];
            r4.x += rr.x; r4.y += rr.y; r4.z += rr.z; r4.w += rr.w;
        }
        *(float4*)&outb[o * L_ + l0 + tx * 4] = r4;
    }
}

__global__ __launch_bounds__(256) void qkv_kernel(
    const float* __restrict__ x, const float* __restrict__ w,
    const float* __restrict__ bias)
{
    int b = blockIdx.z;
    gemm_body<false>(w, x + (size_t)b * C_ * L_, bias, nullptr,
                     g_qkv + (size_t)b * OC3 * L_);
}

__global__ __launch_bounds__(256) void proj_kernel(
    const float* __restrict__ w, const float* __restrict__ bias,
    const float* __restrict__ xres, float* __restrict__ out)
{
    int b = blockIdx.z;
    gemm_body<true>(w, g_attno + (size_t)b * C_ * L_, bias,
                    xres + (size_t)b * C_ * L_, out + (size_t)b * C_ * L_);
}

// ---------------------------------------------------------------------------
// Flash-style fp32 attention. One CTA = one (b,h) x 64 query rows.
// 256 threads as 16x16: score tile 4x4 per thread, output tile 4x2 per thread.
// ---------------------------------------------------------------------------
#define BQ 64
#define BK 64

__global__ __launch_bounds__(256) void attn_kernel()
{
    __shared__ __align__(16) float q_s[BQ][D_ + 1];   // stride 33
    __shared__ __align__(16) float k_s[BK][D_ + 1];   // stride 33
    __shared__ __align__(16) float v_s[BK][D_ + 2];   // stride 34 (even -> float2 loads)
    __shared__ __align__(16) float p_s[BQ][BK + 4];   // stride 68 (16B-multiple -> float4 stores)

    const int tid = threadIdx.x;
    const int ty = tid >> 4;     // row group 0..15 -> rows ty*4..ty*4+3
    const int tx = tid & 15;     // col group 0..15
    const int bh = blockIdx.y;
    const int b = bh >> 2, h = bh & 3;
    const int q0 = blockIdx.x * BQ;

    const float* qb = g_qkv + ((size_t)b * OC3 + h * D_) * L_;
    const float* kb = qb + (size_t)C_ * L_;
    const float* vb = qb + (size_t)(2 * C_) * L_;

    const float scale = 0.17677669529663687f;  // 32^-0.5

    // Load Q tile (pre-scaled)
    #pragma unroll
    for (int i = 0; i < (BQ * D_) / 256; i++) {
        int idx = i * 256 + tid;
        int d = idx >> 6, r = idx & 63;
        q_s[r][d] = qb[d * L_ + q0 + r] * scale;
    }

    float O[4][2] = {};
    float m_run[4], l_run[4];
    #pragma unroll
    for (int i = 0; i < 4; i++) { m_run[i] = -1e30f; l_run[i] = 0.f; }

    for (int kt = 0; kt < L_ / BK; kt++) {
        const int k0 = kt * BK;
        __syncthreads();   // protect k_s/v_s/p_s from previous iteration readers
        #pragma unroll
        for (int i = 0; i < (BK * D_) / 256; i++) {
            int idx = i * 256 + tid;
            int d = idx >> 6, m = idx & 63;
            k_s[m][d] = kb[d * L_ + k0 + m];
            v_s[m][d] = vb[d * L_ + k0 + m];
        }
        __syncthreads();

        // S = Q @ K^T (scaled)
        float s[4][4] = {};
        #pragma unroll
        for (int cc = 0; cc < D_; cc++) {
            float a[4], kv[4];
            #pragma unroll
            for (int i = 0; i < 4; i++) a[i] = q_s[ty * 4 + i][cc];
            #pragma unroll
            for (int j = 0; j < 4; j++) kv[j] = k_s[tx * 4 + j][cc];
            #pragma unroll
            for (int i = 0; i < 4; i++)
                #pragma unroll
                for (int j = 0; j < 4; j++)
                    s[i][j] = fmaf(a[i], kv[j], s[i][j]);
        }

        // Online softmax update per row
        #pragma unroll
        for (int i = 0; i < 4; i++) {
            float mx = fmaxf(fmaxf(s[i][0], s[i][1]), fmaxf(s[i][2], s[i][3]));
            #pragma unroll
            for (int off = 8; off >= 1; off >>= 1)
                mx = fmaxf(mx, __shfl_xor_sync(0xffffffffu, mx, off, 16));
            float m_new = fmaxf(m_run[i], mx);
            float alpha = __expf(m_run[i] - m_new);
            float rs = 0.f;
            #pragma unroll
            for (int j = 0; j < 4; j++) {
                float p = __expf(s[i][j] - m_new);
                s[i][j] = p;
                rs += p;
            }
            #pragma unroll
            for (int off = 8; off >= 1; off >>= 1)
                rs += __shfl_xor_sync(0xffffffffu, rs, off, 16);
            l_run[i] = l_run[i] * alpha + rs;
            m_run[i] = m_new;
            O[i][0] *= alpha;
            O[i][1] *= alpha;
            *(float4*)&p_s[ty * 4 + i][tx * 4] =
                make_float4(s[i][0], s[i][1], s[i][2], s[i][3]);
        }
        __syncthreads();

        // O += P @ V  (each thread: 4 rows x 2 cols)
        #pragma unroll 4
        for (int m = 0; m < BK; m++) {
            float2 vv = *(const float2*)&v_s[m][tx * 2];
            #pragma unroll
            for (int i = 0; i < 4; i++) {
                float p = p_s[ty * 4 + i][m];
                O[i][0] = fmaf(p, vv.x, O[i][0]);
                O[i][1] = fmaf(p, vv.y, O[i][1]);
            }
        }
    }

    // Epilogue: normalize and store transposed to [b][h*32+d][l]
    float* ob = g_attno + ((size_t)b * C_ + h * D_) * L_;
    #pragma unroll
    for (int i = 0; i < 4; i++) {
        float inv = 1.0f / l_run[i];
        int row = q0 + ty * 4 + i;
        #pragma unroll
        for (int j = 0; j < 2; j++) {
            int col = tx * 2 + j;
            ob[(size_t)col * L_ + row] = O[i][j] * inv;
        }
    }
}

// ---------------------------------------------------------------------------
// Launch
// ---------------------------------------------------------------------------
extern "C" void kernel_launch(void* const* d_in, const int* in_sizes, int n_in,
                              void* d_out, int out_size)
{
    const float* x      = (const float*)d_in[0];  // [8][128][2048]
    const float* w_qkv  = (const float*)d_in[1];  // [384][128]
    const float* b_qkv  = (const float*)d_in[2];  // [384]
    const float* w_proj = (const float*)d_in[3];  // [128][128]
    const float* b_proj = (const float*)d_in[4];  // [128]
    float* out = (float*)d_out;                   // [8][128][2048]

    (void)in_sizes; (void)n_in; (void)out_size;

    dim3 g_qkvg(L_ / 64, OC3 / 64, B_);   // 32 x 6 x 8
    qkv_kernel<<<g_qkvg, 256>>>(x, w_qkv, b_qkv);

    dim3 g_attn(L_ / BQ, B_ * H_);        // 32 x 32
    attn_kernel<<<g_attn, 256>>>();

    dim3 g_proj(L_ / 64, C_ / 64, B_);    // 32 x 2 x 8
    proj_kernel<<<g_proj, 256>>>(w_proj, b_proj, x, out);
}

// round 2
// speedup vs baseline: 2.3713x; 2.3713x over previous
#include <cuda_runtime.h>
#include <math.h>
#include <stdint.h>

// Problem constants
#define B_   8
#define C_   128
#define L_   2048
#define H_   4
#define D_   32
#define OC3  384    // 3*C

// Scratch (static device globals — no runtime allocation)
__device__ float g_qkv[B_ * OC3 * L_];     // [b][o][l]
__device__ float g_attno[B_ * C_ * L_];    // [b][h*32+d][l]

// ---------------------------------------------------------------------------
// Generic 1x1-conv GEMM (unchanged from R1 — proven correct, 50+20us)
// ---------------------------------------------------------------------------
template<bool RESID>
__device__ __forceinline__ void gemm_body(
    const float* __restrict__ W, const float* __restrict__ Xb,
    const float* __restrict__ bias, const float* __restrict__ resb,
    float* __restrict__ outb)
{
    __shared__ __align__(16) float w_s[64][33];
    __shared__ __align__(16) float x_s[32][68];

    const int o0 = blockIdx.y * 64;
    const int l0 = blockIdx.x * 64;
    const int tid = threadIdx.x;
    const int ty = tid >> 4;
    const int tx = tid & 15;

    float acc[4][4] = {};

    for (int c0 = 0; c0 < C_; c0 += 32) {
        __syncthreads();
        #pragma unroll
        for (int i = 0; i < 8; i++) {
            int idx = i * 256 + tid;
            int r = idx >> 5, cc = idx & 31;
            w_s[r][cc] = W[(o0 + r) * C_ + c0 + cc];
        }
        #pragma unroll
        for (int i = 0; i < 8; i++) {
            int idx = i * 256 + tid;
            int r = idx >> 6, cl = idx & 63;
            x_s[r][cl] = Xb[(c0 + r) * L_ + l0 + cl];
        }
        __syncthreads();

        #pragma unroll
        for (int cc = 0; cc < 32; cc++) {
            float4 bv = *(const float4*)&x_s[cc][tx * 4];
            float a[4];
            #pragma unroll
            for (int i = 0; i < 4; i++) a[i] = w_s[ty * 4 + i][cc];
            #pragma unroll
            for (int i = 0; i < 4; i++) {
                acc[i][0] = fmaf(a[i], bv.x, acc[i][0]);
                acc[i][1] = fmaf(a[i], bv.y, acc[i][1]);
                acc[i][2] = fmaf(a[i], bv.z, acc[i][2]);
                acc[i][3] = fmaf(a[i], bv.w, acc[i][3]);
            }
        }
    }

    #pragma unroll
    for (int i = 0; i < 4; i++) {
        int o = o0 + ty * 4 + i;
        float bb = bias[o];
        float4 r4;
        r4.x = acc[i][0] + bb;
        r4.y = acc[i][1] + bb;
        r4.z = acc[i][2] + bb;
        r4.w = acc[i][3] + bb;
        if (RESID) {
            float4 rr = *(const float4*)&resb[o * L_ + l0 + tx * 4];
            r4.x += rr.x; r4.y += rr.y; r4.z += rr.z; r4.w += rr.w;
        }
        *(float4*)&outb[o * L_ + l0 + tx * 4] = r4;
    }
}

__global__ __launch_bounds__(256) void qkv_kernel(
    const float* __restrict__ x, const float* __restrict__ w,
    const float* __restrict__ bias)
{
    int b = blockIdx.z;
    gemm_body<false>(w, x + (size_t)b * C_ * L_, bias, nullptr,
                     g_qkv + (size_t)b * OC3 * L_);
}

__global__ __launch_bounds__(256) void proj_kernel(
    const float* __restrict__ w, const float* __restrict__ bias,
    const float* __restrict__ xres, float* __restrict__ out)
{
    int b = blockIdx.z;
    gemm_body<true>(w, g_attno + (size_t)b * C_ * L_, bias,
                    xres + (size_t)b * C_ * L_, out + (size_t)b * C_ * L_);
}

// ---------------------------------------------------------------------------
// TF32 tensor-core flash attention.
// CTA = 128 threads (4 warps), handles one (b,h) x 64 query rows.
// Warp w owns query rows [w*16, w*16+16) x full 64-key width per tile.
// mma.sync.m16n8k8 tf32, fp32 accumulate.
// ---------------------------------------------------------------------------
#define BQ 64
#define BK 64
#define SSTR 68   // smem row stride (floats): 4g+t bank pattern, conflict-light

__device__ __forceinline__ uint32_t f2tf(float f) {
    uint32_t u;
    asm("cvt.rna.tf32.f32 %0, %1;" : "=r"(u) : "f"(f));
    return u;
}

__device__ __forceinline__ void mma8(float d[4], const uint32_t a[4], const uint32_t b[2]) {
    asm volatile(
        "mma.sync.aligned.m16n8k8.row.col.f32.tf32.tf32.f32 "
        "{%0,%1,%2,%3}, {%4,%5,%6,%7}, {%8,%9}, {%0,%1,%2,%3};\n"
        : "+f"(d[0]), "+f"(d[1]), "+f"(d[2]), "+f"(d[3])
        : "r"(a[0]), "r"(a[1]), "r"(a[2]), "r"(a[3]),
          "r"(b[0]), "r"(b[1]));
}

__global__ __launch_bounds__(128) void attn_kernel()
{
    // k_s, v_s: [d=32][m=64] (natural gmem layout, tf32 bits)
    // p_s:      [m=64][k=64] row-major P (tf32 bits); also Q staging [d=32][m=64]
    __shared__ __align__(16) uint32_t k_s[D_ * SSTR];
    __shared__ __align__(16) uint32_t v_s[D_ * SSTR];
    __shared__ __align__(16) uint32_t p_s[BQ * SSTR];

    const int tid  = threadIdx.x;
    const int lane = tid & 31;
    const int warp = tid >> 5;
    const int g    = lane >> 2;    // 0..7
    const int tig  = lane & 3;     // 0..3
    const int m0   = warp * 16;    // query row base for this warp

    const int bh = blockIdx.y;
    const int b  = bh >> 2, h = bh & 3;
    const int q0 = blockIdx.x * BQ;

    const float* qb = g_qkv + ((size_t)b * OC3 + h * D_) * L_;
    const float* kb = qb + (size_t)C_ * L_;
    const float* vb = qb + (size_t)(2 * C_) * L_;

    // fold 1/sqrt(D) and log2(e) into Q so softmax uses raw exp2
    const float qscale = 0.17677669529663687f * 1.4426950408889634f;

    // ---- Stage Q (scaled, tf32) into p_s area, then extract A-fragments ----
    #pragma unroll
    for (int i = 0; i < 4; i++) {
        int idx = i * 128 + tid;            // float4 index over [32][16]
        int d = idx >> 4, m4 = (idx & 15) * 4;
        float4 v = *(const float4*)&qb[(size_t)d * L_ + q0 + m4];
        p_s[d * SSTR + m4 + 0] = f2tf(v.x * qscale);
        p_s[d * SSTR + m4 + 1] = f2tf(v.y * qscale);
        p_s[d * SSTR + m4 + 2] = f2tf(v.z * qscale);
        p_s[d * SSTR + m4 + 3] = f2tf(v.w * qscale);
    }
    __syncthreads();

    uint32_t qf[4][4];   // A-fragments for QK^T, kt = 0..3 (K=32)
    #pragma unroll
    for (int kt = 0; kt < 4; kt++) {
        int kk = kt * 8;
        qf[kt][0] = p_s[(kk + tig) * SSTR + m0 + g];
        qf[kt][1] = p_s[(kk + tig) * SSTR + m0 + g + 8];
        qf[kt][2] = p_s[(kk + tig + 4) * SSTR + m0 + g];
        qf[kt][3] = p_s[(kk + tig + 4) * SSTR + m0 + g + 8];
    }

    float o[4][4] = {};                    // O frags: 4 n-tiles of 8 (D=32)
    float mr0 = -1e30f, mr1 = -1e30f;      // running max, rows g / g+8
    float lr0 = 0.f, lr1 = 0.f;            // running sum

    for (int kt0 = 0; kt0 < L_ / BK; kt0++) {
        const int k0 = kt0 * BK;
        __syncthreads();   // previous iteration consumers done

        // ---- load K,V tiles [32][64] coalesced, convert to tf32 ----
        #pragma unroll
        for (int i = 0; i < 4; i++) {
            int idx = i * 128 + tid;
            int d = idx >> 4, m4 = (idx & 15) * 4;
            float4 kv4 = *(const float4*)&kb[(size_t)d * L_ + k0 + m4];
            float4 vv4 = *(const float4*)&vb[(size_t)d * L_ + k0 + m4];
            k_s[d * SSTR + m4 + 0] = f2tf(kv4.x);
            k_s[d * SSTR + m4 + 1] = f2tf(kv4.y);
            k_s[d * SSTR + m4 + 2] = f2tf(kv4.z);
            k_s[d * SSTR + m4 + 3] = f2tf(kv4.w);
            v_s[d * SSTR + m4 + 0] = f2tf(vv4.x);
            v_s[d * SSTR + m4 + 1] = f2tf(vv4.y);
            v_s[d * SSTR + m4 + 2] = f2tf(vv4.z);
            v_s[d * SSTR + m4 + 3] = f2tf(vv4.w);
        }
        __syncthreads();

        // ---- S = Q K^T : warp computes 16x64, 8 n-tiles x 4 k-steps ----
        float s[8][4] = {};
        #pragma unroll
        for (int kt = 0; kt < 4; kt++) {
            int kk = kt * 8;
            #pragma unroll
            for (int nt = 0; nt < 8; nt++) {
                uint32_t bf[2];
                bf[0] = k_s[(kk + tig) * SSTR + nt * 8 + g];
                bf[1] = k_s[(kk + tig + 4) * SSTR + nt * 8 + g];
                mma8(s[nt], qf[kt], bf);
            }
        }

        // ---- online softmax (rows g and g+8, reduce over lane quad) ----
        float ml0 = -1e30f, ml1 = -1e30f;
        #pragma unroll
        for (int nt = 0; nt < 8; nt++) {
            ml0 = fmaxf(ml0, fmaxf(s[nt][0], s[nt][1]));
            ml1 = fmaxf(ml1, fmaxf(s[nt][2], s[nt][3]));
        }
        ml0 = fmaxf(ml0, __shfl_xor_sync(0xffffffffu, ml0, 1));
        ml0 = fmaxf(ml0, __shfl_xor_sync(0xffffffffu, ml0, 2));
        ml1 = fmaxf(ml1, __shfl_xor_sync(0xffffffffu, ml1, 1));
        ml1 = fmaxf(ml1, __shfl_xor_sync(0xffffffffu, ml1, 2));

        float mn0 = fmaxf(mr0, ml0), mn1 = fmaxf(mr1, ml1);
        float al0 = exp2f(mr0 - mn0), al1 = exp2f(mr1 - mn1);

        float sum0 = 0.f, sum1 = 0.f;
        #pragma unroll
        for (int nt = 0; nt < 8; nt++) {
            float p0 = exp2f(s[nt][0] - mn0);
            float p1 = exp2f(s[nt][1] - mn0);
            float p2 = exp2f(s[nt][2] - mn1);
            float p3 = exp2f(s[nt][3] - mn1);
            sum0 += p0 + p1;
            sum1 += p2 + p3;
            uint32_t* pp = &p_s[(m0 + g) * SSTR + nt * 8 + 2 * tig];
            pp[0] = f2tf(p0); pp[1] = f2tf(p1);
            uint32_t* pq = &p_s[(m0 + g + 8) * SSTR + nt * 8 + 2 * tig];
            pq[0] = f2tf(p2); pq[1] = f2tf(p3);
        }
        sum0 += __shfl_xor_sync(0xffffffffu, sum0, 1);
        sum0 += __shfl_xor_sync(0xffffffffu, sum0, 2);
        sum1 += __shfl_xor_sync(0xffffffffu, sum1, 1);
        sum1 += __shfl_xor_sync(0xffffffffu, sum1, 2);

        lr0 = lr0 * al0 + sum0;
        lr1 = lr1 * al1 + sum1;
        mr0 = mn0; mr1 = mn1;

        #pragma unroll
        for (int nt = 0; nt < 4; nt++) {
            o[nt][0] *= al0; o[nt][1] *= al0;
            o[nt][2] *= al1; o[nt][3] *= al1;
        }
        __syncthreads();   // p_s visible to all lanes of this warp's mma

        // ---- O += P V : 4 n-tiles (D=32) x 8 k-steps (BK=64) ----
        #pragma unroll
        for (int kt = 0; kt < 8; kt++) {
            int kk = kt * 8;
            uint32_t af[4];
            af[0] = p_s[(m0 + g) * SSTR + kk + tig];
            af[1] = p_s[(m0 + g + 8) * SSTR + kk + tig];
            af[2] = p_s[(m0 + g) * SSTR + kk + tig + 4];
            af[3] = p_s[(m0 + g + 8) * SSTR + kk + tig + 4];
            #pragma unroll
            for (int nt = 0; nt < 4; nt++) {
                uint32_t bf[2];
                bf[0] = v_s[(nt * 8 + g) * SSTR + kk + tig];
                bf[1] = v_s[(nt * 8 + g) * SSTR + kk + tig + 4];
                mma8(o[nt], af, bf);
            }
        }
    }

    // ---- epilogue: normalize, store transposed to [b][h*32+d][l] ----
    float* ob = g_attno + ((size_t)b * C_ + h * D_) * L_;
    float i0 = 1.0f / lr0, i1 = 1.0f / lr1;
    int row = q0 + m0 + g;
    #pragma unroll
    for (int nt = 0; nt < 4; nt++) {
        int d = nt * 8 + 2 * tig;
        ob[(size_t)d * L_ + row]           = o[nt][0] * i0;
        ob[(size_t)(d + 1) * L_ + row]     = o[nt][1] * i0;
        ob[(size_t)d * L_ + row + 8]       = o[nt][2] * i1;
        ob[(size_t)(d + 1) * L_ + row + 8] = o[nt][3] * i1;
    }
}

// ---------------------------------------------------------------------------
// Launch
// ---------------------------------------------------------------------------
extern "C" void kernel_launch(void* const* d_in, const int* in_sizes, int n_in,
                              void* d_out, int out_size)
{
    const float* x      = (const float*)d_in[0];
    const float* w_qkv  = (const float*)d_in[1];
    const float* b_qkv  = (const float*)d_in[2];
    const float* w_proj = (const float*)d_in[3];
    const float* b_proj = (const float*)d_in[4];
    float* out = (float*)d_out;

    (void)in_sizes; (void)n_in; (void)out_size;

    dim3 g_qkvg(L_ / 64, OC3 / 64, B_);
    qkv_kernel<<<g_qkvg, 256>>>(x, w_qkv, b_qkv);

    dim3 g_attn(L_ / BQ, B_ * H_);
    attn_kernel<<<g_attn, 128>>>();

    dim3 g_proj(L_ / 64, C_ / 64, B_);
    proj_kernel<<<g_proj, 256>>>(w_proj, b_proj, x, out);
}

// round 3
// speedup vs baseline: 3.1579x; 1.3317x over previous
#include <cuda_runtime.h>
#include <math.h>
#include <stdint.h>

// Problem constants
#define B_   8
#define C_   128
#define L_   2048
#define H_   4
#define D_   32
#define OC3  384    // 3*C

// Scratch (static device globals — no runtime allocation)
__device__ float g_qkv[B_ * OC3 * L_];     // [b][o][l]
__device__ float g_attno[B_ * C_ * L_];    // [b][h*32+d][l]

__device__ __forceinline__ uint32_t fb(float f) { return __float_as_uint(f); }

__device__ __forceinline__ float ex2(float x) {
    float y;
    asm("ex2.approx.f32 %0, %1;" : "=f"(y) : "f"(x));
    return y;
}

__device__ __forceinline__ void mma8(float d[4], const uint32_t a[4], const uint32_t b[2]) {
    asm volatile(
        "mma.sync.aligned.m16n8k8.row.col.f32.tf32.tf32.f32 "
        "{%0,%1,%2,%3}, {%4,%5,%6,%7}, {%8,%9}, {%0,%1,%2,%3};\n"
        : "+f"(d[0]), "+f"(d[1]), "+f"(d[2]), "+f"(d[3])
        : "r"(a[0]), "r"(a[1]), "r"(a[2]), "r"(a[3]),
          "r"(b[0]), "r"(b[1]));
}

// ---------------------------------------------------------------------------
// TF32 tensor-core 1x1-conv GEMM: out[o][l] = W[o][c] X[c][l] + bias (+res)
// CTA = 128(o) x 128(l), 256 threads (8 warps: 4x2), K-chunks of 32.
// ---------------------------------------------------------------------------
template<bool RESID>
__device__ __forceinline__ void gemm_tc(
    const float* __restrict__ W, const float* __restrict__ Xb,
    const float* __restrict__ bias, const float* __restrict__ resb,
    float* __restrict__ outb)
{
    __shared__ __align__(16) float w_s[128 * 36];   // stride 36: banks 4g+tig
    __shared__ __align__(16) float x_s[32 * 136];   // stride 136: banks 8tig+g

    const int o0 = blockIdx.y * 128;
    const int l0 = blockIdx.x * 128;
    const int tid  = threadIdx.x;
    const int lane = tid & 31;
    const int warp = tid >> 5;
    const int g    = lane >> 2;
    const int tig  = lane & 3;
    const int m0w  = (warp >> 1) * 32;
    const int n0w  = (warp & 1) * 64;

    float acc[2][8][4] = {};

    #pragma unroll
    for (int c0 = 0; c0 < 128; c0 += 32) {
        __syncthreads();
        #pragma unroll
        for (int i = 0; i < 4; i++) {
            int idx = i * 256 + tid;
            int r = idx >> 3, c4 = (idx & 7) << 2;
            *(float4*)&w_s[r * 36 + c4] =
                *(const float4*)&W[(o0 + r) * 128 + c0 + c4];
        }
        #pragma unroll
        for (int i = 0; i < 4; i++) {
            int idx = i * 256 + tid;
            int r = idx >> 5, c4 = (idx & 31) << 2;
            *(float4*)&x_s[r * 136 + c4] =
                *(const float4*)&Xb[(size_t)(c0 + r) * L_ + l0 + c4];
        }
        __syncthreads();

        #pragma unroll
        for (int kt = 0; kt < 4; kt++) {
            const int kk = kt * 8;
            uint32_t af[2][4];
            #pragma unroll
            for (int mt = 0; mt < 2; mt++) {
                int row = m0w + mt * 16;
                af[mt][0] = fb(w_s[(row + g) * 36 + kk + tig]);
                af[mt][1] = fb(w_s[(row + g + 8) * 36 + kk + tig]);
                af[mt][2] = fb(w_s[(row + g) * 36 + kk + tig + 4]);
                af[mt][3] = fb(w_s[(row + g + 8) * 36 + kk + tig + 4]);
            }
            uint32_t bf[8][2];
            #pragma unroll
            for (int nt = 0; nt < 8; nt++) {
                bf[nt][0] = fb(x_s[(kk + tig) * 136 + n0w + nt * 8 + g]);
                bf[nt][1] = fb(x_s[(kk + tig + 4) * 136 + n0w + nt * 8 + g]);
            }
            #pragma unroll
            for (int mt = 0; mt < 2; mt++)
                #pragma unroll
                for (int nt = 0; nt < 8; nt++)
                    mma8(acc[mt][nt], af[mt], bf[nt]);
        }
    }

    #pragma unroll
    for (int mt = 0; mt < 2; mt++) {
        int r0 = o0 + m0w + mt * 16 + g;
        int r1 = r0 + 8;
        float b0 = bias[r0], b1 = bias[r1];
        #pragma unroll
        for (int nt = 0; nt < 8; nt++) {
            int cl = l0 + n0w + nt * 8 + 2 * tig;
            float2 v0, v1;
            v0.x = acc[mt][nt][0] + b0; v0.y = acc[mt][nt][1] + b0;
            v1.x = acc[mt][nt][2] + b1; v1.y = acc[mt][nt][3] + b1;
            if (RESID) {
                float2 q0r = *(const float2*)&resb[(size_t)r0 * L_ + cl];
                float2 q1r = *(const float2*)&resb[(size_t)r1 * L_ + cl];
                v0.x += q0r.x; v0.y += q0r.y;
                v1.x += q1r.x; v1.y += q1r.y;
            }
            *(float2*)&outb[(size_t)r0 * L_ + cl] = v0;
            *(float2*)&outb[(size_t)r1 * L_ + cl] = v1;
        }
    }
}

__global__ __launch_bounds__(256, 2) void qkv_kernel(
    const float* __restrict__ x, const float* __restrict__ w,
    const float* __restrict__ bias)
{
    int b = blockIdx.z;
    gemm_tc<false>(w, x + (size_t)b * C_ * L_, bias, nullptr,
                   g_qkv + (size_t)b * OC3 * L_);
}

__global__ __launch_bounds__(256, 2) void proj_kernel(
    const float* __restrict__ w, const float* __restrict__ bias,
    const float* __restrict__ xres, float* __restrict__ out)
{
    int b = blockIdx.z;
    gemm_tc<true>(w, g_attno + (size_t)b * C_ * L_, bias,
                  xres + (size_t)b * C_ * L_, out + (size_t)b * C_ * L_);
}

// ---------------------------------------------------------------------------
// TF32 flash attention. CTA = 128 threads (4 warps), 128 query rows.
// Warp owns 32 rows (2 m-tiles); K-fragments cached in regs across m-tiles.
// Dynamic smem: P[128][68] (8704) | K[32][136] (4352) | V[32][132] (4224)
// ---------------------------------------------------------------------------
#define BQ 128
#define BK 64
#define KSTR 136
#define VSTR 132
#define PSTR 68

__global__ __launch_bounds__(128) void attn_kernel()
{
    extern __shared__ __align__(16) float sm[];
    float* p_s = sm;                    // also Q staging [32][136]
    float* k_s = sm + BQ * PSTR;        // +8704
    float* v_s = k_s + D_ * KSTR;       // +4352

    const int tid  = threadIdx.x;
    const int lane = tid & 31;
    const int warp = tid >> 5;
    const int g    = lane >> 2;
    const int tig  = lane & 3;
    const int m0   = warp * 32;

    const int bh = blockIdx.y;
    const int b  = bh >> 2, h = bh & 3;
    const int q0 = blockIdx.x * BQ;

    const float* qb = g_qkv + ((size_t)b * OC3 + h * D_) * L_;
    const float* kb = qb + (size_t)C_ * L_;
    const float* vb = qb + (size_t)(2 * C_) * L_;

    const float qscale = 0.17677669529663687f * 1.4426950408889634f;

    // ---- Stage Q (scaled) [32][128] at stride 136 ----
    #pragma unroll
    for (int i = 0; i < 8; i++) {
        int idx = i * 128 + tid;            // float4 index
        int d = idx >> 5, m4 = (idx & 31) << 2;
        float4 v = *(const float4*)&qb[(size_t)d * L_ + q0 + m4];
        v.x *= qscale; v.y *= qscale; v.z *= qscale; v.w *= qscale;
        *(float4*)&p_s[d * KSTR + m4] = v;
    }
    __syncthreads();

    uint32_t qf[2][4][4];
    #pragma unroll
    for (int mt = 0; mt < 2; mt++) {
        int mb = m0 + mt * 16;
        #pragma unroll
        for (int kt = 0; kt < 4; kt++) {
            int kk = kt * 8;
            qf[mt][kt][0] = fb(p_s[(kk + tig) * KSTR + mb + g]);
            qf[mt][kt][1] = fb(p_s[(kk + tig) * KSTR + mb + g + 8]);
            qf[mt][kt][2] = fb(p_s[(kk + tig + 4) * KSTR + mb + g]);
            qf[mt][kt][3] = fb(p_s[(kk + tig + 4) * KSTR + mb + g + 8]);
        }
    }

    float o[2][4][4] = {};
    float mr[2][2], lr[2][2];
    #pragma unroll
    for (int mt = 0; mt < 2; mt++) {
        mr[mt][0] = mr[mt][1] = -1e30f;
        lr[mt][0] = lr[mt][1] = 0.f;
    }

    for (int t = 0; t < L_ / BK; t++) {
        const int k0 = t * BK;
        __syncthreads();   // prior tile's V readers done

        #pragma unroll
        for (int i = 0; i < 4; i++) {
            int idx = i * 128 + tid;        // float4 over [32][16]
            int d = idx >> 4, m4 = (idx & 15) << 2;
            *(float4*)&k_s[d * KSTR + m4] =
                *(const float4*)&kb[(size_t)d * L_ + k0 + m4];
            *(float4*)&v_s[d * VSTR + m4] =
                *(const float4*)&vb[(size_t)d * L_ + k0 + m4];
        }
        __syncthreads();

        // K fragments: load once, reuse across both m-tiles
        uint32_t kf[4][8][2];
        #pragma unroll
        for (int kt = 0; kt < 4; kt++) {
            int kk = kt * 8;
            #pragma unroll
            for (int nt = 0; nt < 8; nt++) {
                kf[kt][nt][0] = fb(k_s[(kk + tig) * KSTR + nt * 8 + g]);
                kf[kt][nt][1] = fb(k_s[(kk + tig + 4) * KSTR + nt * 8 + g]);
            }
        }

        #pragma unroll
        for (int mt = 0; mt < 2; mt++) {
            const int mb = m0 + mt * 16;
            float s[8][4] = {};
            #pragma unroll
            for (int kt = 0; kt < 4; kt++)
                #pragma unroll
                for (int nt = 0; nt < 8; nt++)
                    mma8(s[nt], qf[mt][kt], kf[kt][nt]);

            float ml0 = -1e30f, ml1 = -1e30f;
            #pragma unroll
            for (int nt = 0; nt < 8; nt++) {
                ml0 = fmaxf(ml0, fmaxf(s[nt][0], s[nt][1]));
                ml1 = fmaxf(ml1, fmaxf(s[nt][2], s[nt][3]));
            }
            ml0 = fmaxf(ml0, __shfl_xor_sync(0xffffffffu, ml0, 1));
            ml0 = fmaxf(ml0, __shfl_xor_sync(0xffffffffu, ml0, 2));
            ml1 = fmaxf(ml1, __shfl_xor_sync(0xffffffffu, ml1, 1));
            ml1 = fmaxf(ml1, __shfl_xor_sync(0xffffffffu, ml1, 2));

            float mn0 = fmaxf(mr[mt][0], ml0), mn1 = fmaxf(mr[mt][1], ml1);
            float al0 = ex2(mr[mt][0] - mn0), al1 = ex2(mr[mt][1] - mn1);

            float sum0 = 0.f, sum1 = 0.f;
            #pragma unroll
            for (int nt = 0; nt < 8; nt++) {
                float p0 = ex2(s[nt][0] - mn0);
                float p1 = ex2(s[nt][1] - mn0);
                float p2 = ex2(s[nt][2] - mn1);
                float p3 = ex2(s[nt][3] - mn1);
                sum0 += p0 + p1;
                sum1 += p2 + p3;
                float2 w0; w0.x = p0; w0.y = p1;
                float2 w1; w1.x = p2; w1.y = p3;
                *(float2*)&p_s[(mb + g) * PSTR + nt * 8 + 2 * tig] = w0;
                *(float2*)&p_s[(mb + g + 8) * PSTR + nt * 8 + 2 * tig] = w1;
            }
            sum0 += __shfl_xor_sync(0xffffffffu, sum0, 1);
            sum0 += __shfl_xor_sync(0xffffffffu, sum0, 2);
            sum1 += __shfl_xor_sync(0xffffffffu, sum1, 1);
            sum1 += __shfl_xor_sync(0xffffffffu, sum1, 2);

            lr[mt][0] = lr[mt][0] * al0 + sum0;
            lr[mt][1] = lr[mt][1] * al1 + sum1;
            mr[mt][0] = mn0; mr[mt][1] = mn1;

            #pragma unroll
            for (int nt = 0; nt < 4; nt++) {
                o[mt][nt][0] *= al0; o[mt][nt][1] *= al0;
                o[mt][nt][2] *= al1; o[mt][nt][3] *= al1;
            }
        }
        __syncwarp();   // warp's own P stores visible to its mma operand loads

        // ---- O += P V : P rows are warp-private, no CTA barrier needed ----
        #pragma unroll
        for (int kt = 0; kt < 8; kt++) {
            const int kk = kt * 8;
            uint32_t af[2][4];
            #pragma unroll
            for (int mt = 0; mt < 2; mt++) {
                int mb = m0 + mt * 16;
                af[mt][0] = fb(p_s[(mb + g) * PSTR + kk + tig]);
                af[mt][1] = fb(p_s[(mb + g + 8) * PSTR + kk + tig]);
                af[mt][2] = fb(p_s[(mb + g) * PSTR + kk + tig + 4]);
                af[mt][3] = fb(p_s[(mb + g + 8) * PSTR + kk + tig + 4]);
            }
            #pragma unroll
            for (int nt = 0; nt < 4; nt++) {
                uint32_t bfv[2];
                bfv[0] = fb(v_s[(nt * 8 + g) * VSTR + kk + tig]);
                bfv[1] = fb(v_s[(nt * 8 + g) * VSTR + kk + tig + 4]);
                #pragma unroll
                for (int mt = 0; mt < 2; mt++)
                    mma8(o[mt][nt], af[mt], bfv);
            }
        }
    }

    // ---- epilogue: normalize, store transposed to [b][h*32+d][l] ----
    float* ob = g_attno + ((size_t)b * C_ + h * D_) * L_;
    #pragma unroll
    for (int mt = 0; mt < 2; mt++) {
        float i0 = 1.0f / lr[mt][0], i1 = 1.0f / lr[mt][1];
        int row = q0 + m0 + mt * 16 + g;
        #pragma unroll
        for (int nt = 0; nt < 4; nt++) {
            int d = nt * 8 + 2 * tig;
            ob[(size_t)d * L_ + row]           = o[mt][nt][0] * i0;
            ob[(size_t)(d + 1) * L_ + row]     = o[mt][nt][1] * i0;
            ob[(size_t)d * L_ + row + 8]       = o[mt][nt][2] * i1;
            ob[(size_t)(d + 1) * L_ + row + 8] = o[mt][nt][3] * i1;
        }
    }
}

// ---------------------------------------------------------------------------
// Launch
// ---------------------------------------------------------------------------
#define ATTN_SMEM ((BQ * PSTR + D_ * KSTR + D_ * VSTR) * 4)

extern "C" void kernel_launch(void* const* d_in, const int* in_sizes, int n_in,
                              void* d_out, int out_size)
{
    const float* x      = (const float*)d_in[0];
    const float* w_qkv  = (const float*)d_in[1];
    const float* b_qkv  = (const float*)d_in[2];
    const float* w_proj = (const float*)d_in[3];
    const float* b_proj = (const float*)d_in[4];
    float* out = (float*)d_out;

    (void)in_sizes; (void)n_in; (void)out_size;

    cudaFuncSetAttribute(attn_kernel,
                         cudaFuncAttributeMaxDynamicSharedMemorySize, ATTN_SMEM);

    dim3 g_qkvg(L_ / 128, OC3 / 128, B_);   // 16 x 3 x 8
    qkv_kernel<<<g_qkvg, 256>>>(x, w_qkv, b_qkv);

    dim3 g_attn(L_ / BQ, B_ * H_);          // 16 x 32
    attn_kernel<<<g_attn, 128, ATTN_SMEM>>>();

    dim3 g_proj(L_ / 128, C_ / 128, B_);    // 16 x 1 x 8
    proj_kernel<<<g_proj, 256>>>(w_proj, b_proj, x, out);
}

// round 4
// speedup vs baseline: 3.3373x; 1.0568x over previous
#include <cuda_runtime.h>
#include <math.h>
#include <stdint.h>

// Problem constants
#define B_   8
#define C_   128
#define L_   2048
#define H_   4
#define D_   32
#define OC3  384    // 3*C

// Scratch (static device globals — no runtime allocation)
__device__ float g_qkv[B_ * OC3 * L_];     // [b][o][l]
__device__ float g_attno[B_ * C_ * L_];    // [b][h*32+d][l]

__device__ __forceinline__ uint32_t fb(float f) { return __float_as_uint(f); }

__device__ __forceinline__ float ex2(float x) {
    float y;
    asm("ex2.approx.f32 %0, %1;" : "=f"(y) : "f"(x));
    return y;
}

__device__ __forceinline__ void mma8(float d[4], const uint32_t a[4], const uint32_t b[2]) {
    asm volatile(
        "mma.sync.aligned.m16n8k8.row.col.f32.tf32.tf32.f32 "
        "{%0,%1,%2,%3}, {%4,%5,%6,%7}, {%8,%9}, {%0,%1,%2,%3};\n"
        : "+f"(d[0]), "+f"(d[1]), "+f"(d[2]), "+f"(d[3])
        : "r"(a[0]), "r"(a[1]), "r"(a[2]), "r"(a[3]),
          "r"(b[0]), "r"(b[1]));
}

__device__ __forceinline__ void cp16(uint32_t saddr, const void* g) {
    asm volatile("cp.async.cg.shared.global [%0], [%1], 16;" :: "r"(saddr), "l"(g));
}
#define CP_COMMIT() asm volatile("cp.async.commit_group;")
#define CP_WAIT(n)  asm volatile("cp.async.wait_group %0;" :: "n"(n))

// ---------------------------------------------------------------------------
// TF32 tensor-core 1x1-conv GEMM with cp.async double buffering.
// CTA = 128(o) x 128(l), 256 threads (8 warps: 4x2), K-chunks of 32.
// Dynamic smem: w_s[2][128*36] | x_s[2][32*136]  (70KB)
// ---------------------------------------------------------------------------
#define WCH (128 * 36)
#define XCH (32 * 136)

template<bool RESID>
__device__ __forceinline__ void gemm_tc(
    const float* __restrict__ W, const float* __restrict__ Xb,
    const float* __restrict__ bias, const float* __restrict__ resb,
    float* __restrict__ outb)
{
    extern __shared__ __align__(16) float gsm[];
    float* w_s = gsm;                 // [2][WCH]
    float* x_s = gsm + 2 * WCH;       // [2][XCH]

    const int o0 = blockIdx.y * 128;
    const int l0 = blockIdx.x * 128;
    const int tid  = threadIdx.x;
    const int lane = tid & 31;
    const int warp = tid >> 5;
    const int g    = lane >> 2;
    const int tig  = lane & 3;
    const int m0w  = (warp >> 1) * 32;
    const int n0w  = (warp & 1) * 64;

    // per-thread load slots
    const int wr = tid >> 3, wc4 = (tid & 7) << 2;          // +32 rows per i
    const int xr = tid >> 5, xc4 = (tid & 31) << 2;         // +8 rows per i

    uint32_t wbase = (uint32_t)__cvta_generic_to_shared(w_s);
    uint32_t xbase = (uint32_t)__cvta_generic_to_shared(x_s);

    // prologue: chunk 0 -> buf 0
    #pragma unroll
    for (int i = 0; i < 4; i++) {
        cp16(wbase + ((wr + i * 32) * 36 + wc4) * 4,
             &W[(o0 + wr + i * 32) * 128 + wc4]);
        cp16(xbase + ((xr + i * 8) * 136 + xc4) * 4,
             &Xb[(size_t)(xr + i * 8) * L_ + l0 + xc4]);
    }
    CP_COMMIT();

    float acc[2][8][4] = {};

    #pragma unroll
    for (int kc = 0; kc < 4; kc++) {
        const int buf = kc & 1;
        if (kc < 3) {
            const int c0n = (kc + 1) * 32;
            const int nb = (kc + 1) & 1;
            #pragma unroll
            for (int i = 0; i < 4; i++) {
                cp16(wbase + (nb * WCH + (wr + i * 32) * 36 + wc4) * 4,
                     &W[(o0 + wr + i * 32) * 128 + c0n + wc4]);
                cp16(xbase + (nb * XCH + (xr + i * 8) * 136 + xc4) * 4,
                     &Xb[(size_t)(c0n + xr + i * 8) * L_ + l0 + xc4]);
            }
            CP_COMMIT();
            CP_WAIT(1);
        } else {
            CP_WAIT(0);
        }
        __syncthreads();

        const float* ws = w_s + buf * WCH;
        const float* xs = x_s + buf * XCH;
        #pragma unroll
        for (int kt = 0; kt < 4; kt++) {
            const int kk = kt * 8;
            uint32_t af[2][4];
            #pragma unroll
            for (int mt = 0; mt < 2; mt++) {
                int row = m0w + mt * 16;
                af[mt][0] = fb(ws[(row + g) * 36 + kk + tig]);
                af[mt][1] = fb(ws[(row + g + 8) * 36 + kk + tig]);
                af[mt][2] = fb(ws[(row + g) * 36 + kk + tig + 4]);
                af[mt][3] = fb(ws[(row + g + 8) * 36 + kk + tig + 4]);
            }
            uint32_t bf[8][2];
            #pragma unroll
            for (int nt = 0; nt < 8; nt++) {
                bf[nt][0] = fb(xs[(kk + tig) * 136 + n0w + nt * 8 + g]);
                bf[nt][1] = fb(xs[(kk + tig + 4) * 136 + n0w + nt * 8 + g]);
            }
            #pragma unroll
            for (int mt = 0; mt < 2; mt++)
                #pragma unroll
                for (int nt = 0; nt < 8; nt++)
                    mma8(acc[mt][nt], af[mt], bf[nt]);
        }
        __syncthreads();
    }

    #pragma unroll
    for (int mt = 0; mt < 2; mt++) {
        int r0 = o0 + m0w + mt * 16 + g;
        int r1 = r0 + 8;
        float b0 = bias[r0], b1 = bias[r1];
        #pragma unroll
        for (int nt = 0; nt < 8; nt++) {
            int cl = l0 + n0w + nt * 8 + 2 * tig;
            float2 v0, v1;
            v0.x = acc[mt][nt][0] + b0; v0.y = acc[mt][nt][1] + b0;
            v1.x = acc[mt][nt][2] + b1; v1.y = acc[mt][nt][3] + b1;
            if (RESID) {
                float2 q0r = *(const float2*)&resb[(size_t)r0 * L_ + cl];
                float2 q1r = *(const float2*)&resb[(size_t)r1 * L_ + cl];
                v0.x += q0r.x; v0.y += q0r.y;
                v1.x += q1r.x; v1.y += q1r.y;
            }
            *(float2*)&outb[(size_t)r0 * L_ + cl] = v0;
            *(float2*)&outb[(size_t)r1 * L_ + cl] = v1;
        }
    }
}

#define GEMM_SMEM ((2 * WCH + 2 * XCH) * 4)

__global__ __launch_bounds__(256) void qkv_kernel(
    const float* __restrict__ x, const float* __restrict__ w,
    const float* __restrict__ bias)
{
    int b = blockIdx.z;
    gemm_tc<false>(w, x + (size_t)b * C_ * L_, bias, nullptr,
                   g_qkv + (size_t)b * OC3 * L_);
}

__global__ __launch_bounds__(256) void proj_kernel(
    const float* __restrict__ w, const float* __restrict__ bias,
    const float* __restrict__ xres, float* __restrict__ out)
{
    int b = blockIdx.z;
    gemm_tc<true>(w, g_attno + (size_t)b * C_ * L_, bias,
                  xres + (size_t)b * C_ * L_, out + (size_t)b * C_ * L_);
}

// ---------------------------------------------------------------------------
// TF32 flash attention with cp.async double-buffered K/V.
// CTA = 128 threads (4 warps), 128 query rows; warp owns 32 rows.
// Dynamic smem: P[128][68] | K[2][32][136] | V[2][32][132]  (103KB)
// ---------------------------------------------------------------------------
#define BQ 128
#define BK 64
#define KSTR 136
#define VSTR 132
#define PSTR 68
#define KCH (D_ * KSTR)
#define VCH (D_ * VSTR)

__global__ __launch_bounds__(128) void attn_kernel()
{
    extern __shared__ __align__(16) float sm[];
    float* p_s = sm;                     // also Q staging [32][136]
    float* k_s = sm + BQ * PSTR;
    float* v_s = k_s + 2 * KCH;

    const int tid  = threadIdx.x;
    const int lane = tid & 31;
    const int warp = tid >> 5;
    const int g    = lane >> 2;
    const int tig  = lane & 3;
    const int m0   = warp * 32;

    const int bh = blockIdx.y;
    const int b  = bh >> 2, h = bh & 3;
    const int q0 = blockIdx.x * BQ;

    const float* qb = g_qkv + ((size_t)b * OC3 + h * D_) * L_;
    const float* kb = qb + (size_t)C_ * L_;
    const float* vb = qb + (size_t)(2 * C_) * L_;

    const float qscale = 0.17677669529663687f * 1.4426950408889634f;

    uint32_t kbase = (uint32_t)__cvta_generic_to_shared(k_s);
    uint32_t vbase = (uint32_t)__cvta_generic_to_shared(v_s);

    // per-thread K/V load slots: 512 float4 per tile, 4 per thread per tensor
    const int ld_d = tid >> 4;            // +8 per i
    const int ld_m4 = (tid & 15) << 2;

    // prologue: tile 0 -> buf 0
    #pragma unroll
    for (int i = 0; i < 4; i++) {
        int d = ld_d + i * 8;
        cp16(kbase + (d * KSTR + ld_m4) * 4, &kb[(size_t)d * L_ + ld_m4]);
        cp16(vbase + (d * VSTR + ld_m4) * 4, &vb[(size_t)d * L_ + ld_m4]);
    }
    CP_COMMIT();

    // ---- Stage Q (scaled) [32][128] at stride 136 in p_s ----
    #pragma unroll
    for (int i = 0; i < 8; i++) {
        int idx = i * 128 + tid;
        int d = idx >> 5, m4 = (idx & 31) << 2;
        float4 v = *(const float4*)&qb[(size_t)d * L_ + q0 + m4];
        v.x *= qscale; v.y *= qscale; v.z *= qscale; v.w *= qscale;
        *(float4*)&p_s[d * KSTR + m4] = v;
    }
    __syncthreads();

    uint32_t qf[2][4][4];
    #pragma unroll
    for (int mt = 0; mt < 2; mt++) {
        int mb = m0 + mt * 16;
        #pragma unroll
        for (int kt = 0; kt < 4; kt++) {
            int kk = kt * 8;
            qf[mt][kt][0] = fb(p_s[(kk + tig) * KSTR + mb + g]);
            qf[mt][kt][1] = fb(p_s[(kk + tig) * KSTR + mb + g + 8]);
            qf[mt][kt][2] = fb(p_s[(kk + tig + 4) * KSTR + mb + g]);
            qf[mt][kt][3] = fb(p_s[(kk + tig + 4) * KSTR + mb + g + 8]);
        }
    }
    __syncthreads();   // Q staging area (p_s) free for P use

    float o[2][4][4] = {};
    float mr[2][2], lr[2][2];
    #pragma unroll
    for (int mt = 0; mt < 2; mt++) {
        mr[mt][0] = mr[mt][1] = -1e30f;
        lr[mt][0] = lr[mt][1] = 0.f;
    }

    for (int t = 0; t < L_ / BK; t++) {
        const int buf = t & 1;

        if (t < L_ / BK - 1) {
            const int k0n = (t + 1) * BK;
            const int nb = (t + 1) & 1;
            #pragma unroll
            for (int i = 0; i < 4; i++) {
                int d = ld_d + i * 8;
                cp16(kbase + (nb * KCH + d * KSTR + ld_m4) * 4,
                     &kb[(size_t)d * L_ + k0n + ld_m4]);
                cp16(vbase + (nb * VCH + d * VSTR + ld_m4) * 4,
                     &vb[(size_t)d * L_ + k0n + ld_m4]);
            }
            CP_COMMIT();
            CP_WAIT(1);
        } else {
            CP_WAIT(0);
        }
        __syncthreads();

        const float* ks = k_s + buf * KCH;
        const float* vs = v_s + buf * VCH;

        // K fragments: load once, reuse across both m-tiles
        uint32_t kf[4][8][2];
        #pragma unroll
        for (int kt = 0; kt < 4; kt++) {
            int kk = kt * 8;
            #pragma unroll
            for (int nt = 0; nt < 8; nt++) {
                kf[kt][nt][0] = fb(ks[(kk + tig) * KSTR + nt * 8 + g]);
                kf[kt][nt][1] = fb(ks[(kk + tig + 4) * KSTR + nt * 8 + g]);
            }
        }

        #pragma unroll
        for (int mt = 0; mt < 2; mt++) {
            const int mb = m0 + mt * 16;
            float s[8][4] = {};
            #pragma unroll
            for (int kt = 0; kt < 4; kt++)
                #pragma unroll
                for (int nt = 0; nt < 8; nt++)
                    mma8(s[nt], qf[mt][kt], kf[kt][nt]);

            float ml0 = -1e30f, ml1 = -1e30f;
            #pragma unroll
            for (int nt = 0; nt < 8; nt++) {
                ml0 = fmaxf(ml0, fmaxf(s[nt][0], s[nt][1]));
                ml1 = fmaxf(ml1, fmaxf(s[nt][2], s[nt][3]));
            }
            ml0 = fmaxf(ml0, __shfl_xor_sync(0xffffffffu, ml0, 1));
            ml0 = fmaxf(ml0, __shfl_xor_sync(0xffffffffu, ml0, 2));
            ml1 = fmaxf(ml1, __shfl_xor_sync(0xffffffffu, ml1, 1));
            ml1 = fmaxf(ml1, __shfl_xor_sync(0xffffffffu, ml1, 2));

            float mn0 = fmaxf(mr[mt][0], ml0), mn1 = fmaxf(mr[mt][1], ml1);
            float al0 = ex2(mr[mt][0] - mn0), al1 = ex2(mr[mt][1] - mn1);

            float sum0 = 0.f, sum1 = 0.f;
            #pragma unroll
            for (int nt = 0; nt < 8; nt++) {
                float p0 = ex2(s[nt][0] - mn0);
                float p1 = ex2(s[nt][1] - mn0);
                float p2 = ex2(s[nt][2] - mn1);
                float p3 = ex2(s[nt][3] - mn1);
                sum0 += p0 + p1;
                sum1 += p2 + p3;
                float2 w0; w0.x = p0; w0.y = p1;
                float2 w1; w1.x = p2; w1.y = p3;
                *(float2*)&p_s[(mb + g) * PSTR + nt * 8 + 2 * tig] = w0;
                *(float2*)&p_s[(mb + g + 8) * PSTR + nt * 8 + 2 * tig] = w1;
            }
            sum0 += __shfl_xor_sync(0xffffffffu, sum0, 1);
            sum0 += __shfl_xor_sync(0xffffffffu, sum0, 2);
            sum1 += __shfl_xor_sync(0xffffffffu, sum1, 1);
            sum1 += __shfl_xor_sync(0xffffffffu, sum1, 2);

            lr[mt][0] = lr[mt][0] * al0 + sum0;
            lr[mt][1] = lr[mt][1] * al1 + sum1;
            mr[mt][0] = mn0; mr[mt][1] = mn1;

            #pragma unroll
            for (int nt = 0; nt < 4; nt++) {
                o[mt][nt][0] *= al0; o[mt][nt][1] *= al0;
                o[mt][nt][2] *= al1; o[mt][nt][3] *= al1;
            }
        }
        __syncwarp();   // warp's own P stores visible to its mma operand loads

        // ---- O += P V : P rows are warp-private, no CTA barrier needed ----
        #pragma unroll
        for (int kt = 0; kt < 8; kt++) {
            const int kk = kt * 8;
            uint32_t af[2][4];
            #pragma unroll
            for (int mt = 0; mt < 2; mt++) {
                int mb = m0 + mt * 16;
                af[mt][0] = fb(p_s[(mb + g) * PSTR + kk + tig]);
                af[mt][1] = fb(p_s[(mb + g + 8) * PSTR + kk + tig]);
                af[mt][2] = fb(p_s[(mb + g) * PSTR + kk + tig + 4]);
                af[mt][3] = fb(p_s[(mb + g + 8) * PSTR + kk + tig + 4]);
            }
            #pragma unroll
            for (int nt = 0; nt < 4; nt++) {
                uint32_t bfv[2];
                bfv[0] = fb(vs[(nt * 8 + g) * VSTR + kk + tig]);
                bfv[1] = fb(vs[(nt * 8 + g) * VSTR + kk + tig + 4]);
                #pragma unroll
                for (int mt = 0; mt < 2; mt++)
                    mma8(o[mt][nt], af[mt], bfv);
            }
        }
        __syncthreads();   // all reads of buf done before it is re-filled
    }

    // ---- epilogue: normalize, store transposed to [b][h*32+d][l] ----
    float* ob = g_attno + ((size_t)b * C_ + h * D_) * L_;
    #pragma unroll
    for (int mt = 0; mt < 2; mt++) {
        float i0 = 1.0f / lr[mt][0], i1 = 1.0f / lr[mt][1];
        int row = q0 + m0 + mt * 16 + g;
        #pragma unroll
        for (int nt = 0; nt < 4; nt++) {
            int d = nt * 8 + 2 * tig;
            ob[(size_t)d * L_ + row]           = o[mt][nt][0] * i0;
            ob[(size_t)(d + 1) * L_ + row]     = o[mt][nt][1] * i0;
            ob[(size_t)d * L_ + row + 8]       = o[mt][nt][2] * i1;
            ob[(size_t)(d + 1) * L_ + row + 8] = o[mt][nt][3] * i1;
        }
    }
}

#define ATTN_SMEM ((BQ * PSTR + 2 * KCH + 2 * VCH) * 4)

// ---------------------------------------------------------------------------
// Launch
// ---------------------------------------------------------------------------
extern "C" void kernel_launch(void* const* d_in, const int* in_sizes, int n_in,
                              void* d_out, int out_size)
{
    const float* x      = (const float*)d_in[0];
    const float* w_qkv  = (const float*)d_in[1];
    const float* b_qkv  = (const float*)d_in[2];
    const float* w_proj = (const float*)d_in[3];
    const float* b_proj = (const float*)d_in[4];
    float* out = (float*)d_out;

    (void)in_sizes; (void)n_in; (void)out_size;

    static int attr_done = 0;
    if (!attr_done) {
        cudaFuncSetAttribute(attn_kernel,
                             cudaFuncAttributeMaxDynamicSharedMemorySize, ATTN_SMEM);
        cudaFuncSetAttribute(qkv_kernel,
                             cudaFuncAttributeMaxDynamicSharedMemorySize, GEMM_SMEM);
        cudaFuncSetAttribute(proj_kernel,
                             cudaFuncAttributeMaxDynamicSharedMemorySize, GEMM_SMEM);
        attr_done = 1;
    }

    dim3 g_qkvg(L_ / 128, OC3 / 128, B_);   // 16 x 3 x 8
    qkv_kernel<<<g_qkvg, 256, GEMM_SMEM>>>(x, w_qkv, b_qkv);

    dim3 g_attn(L_ / BQ, B_ * H_);          // 16 x 32
    attn_kernel<<<g_attn, 128, ATTN_SMEM>>>();

    dim3 g_proj(L_ / 128, C_ / 128, B_);    // 16 x 1 x 8
    proj_kernel<<<g_proj, 256, GEMM_SMEM>>>(w_proj, b_proj, x, out);
}